// round 16
// baseline (speedup 1.0000x reference)
#include <cuda_runtime.h>
#include <cstdint>

// Problem constants
#define BATCH 8
#define NPTS  32768
#define MPTS  (NPTS / 4)     // 8192
#define CINCH 128
#define MROWS (3 + CINCH)    // 131 output rows per batch

// FPS kernel config: one cluster of CSZ CTAs per batch
#define CSZ   8
#define TPB   512
#define PPC   (NPTS / CSZ)           // points per CTA = 4096
#define PPT   (PPC / TPB)            // points per thread = 8
#define NPAIR (PPT / 2)              // f32x2 pairs per thread = 4
#define NWARP (TPB / 32)             // 16

// ---------------- helpers ----------------
__device__ __forceinline__ unsigned smem_u32(const void* p) {
    return (unsigned)__cvta_generic_to_shared(p);
}
__device__ __forceinline__ void cluster_sync_() {
    asm volatile("barrier.cluster.arrive.aligned;" ::: "memory");
    asm volatile("barrier.cluster.wait.aligned;" ::: "memory");
}
__device__ __forceinline__ unsigned mapa_rank(unsigned local_addr, int r) {
    unsigned ret;
    asm("mapa.shared::cluster.u32 %0, %1, %2;" : "=r"(ret) : "r"(local_addr), "r"(r));
    return ret;
}
__device__ __forceinline__ void st_cluster_u64(unsigned addr, unsigned long long v) {
    asm volatile("st.shared::cluster.b64 [%0], %1;" :: "r"(addr), "l"(v) : "memory");
}
__device__ __forceinline__ unsigned cluster_rank_() {
    unsigned r;
    asm("mov.u32 %0, %%cluster_ctarank;" : "=r"(r));
    return r;
}
__device__ __forceinline__ unsigned redux_max_u32(unsigned v) {
    unsigned r;
    asm volatile("redux.sync.max.u32 %0, %1, 0xffffffff;" : "=r"(r) : "r"(v));
    return r;
}
__device__ __forceinline__ unsigned redux_min_u32(unsigned v) {
    unsigned r;
    asm volatile("redux.sync.min.u32 %0, %1, 0xffffffff;" : "=r"(r) : "r"(v));
    return r;
}

// mbarrier ops
__device__ __forceinline__ void mbar_init(unsigned addr, unsigned count) {
    asm volatile("mbarrier.init.shared.b64 [%0], %1;" :: "r"(addr), "r"(count) : "memory");
}
__device__ __forceinline__ void mbar_arrive_remote(unsigned remote_addr) {
    asm volatile("mbarrier.arrive.release.cluster.shared::cluster.b64 _, [%0];"
                 :: "r"(remote_addr) : "memory");
}
__device__ __forceinline__ void mbar_wait(unsigned addr, unsigned parity) {
    asm volatile(
        "{\n\t"
        ".reg .pred P;\n\t"
        "WAIT_%=: \n\t"
        "mbarrier.try_wait.parity.acquire.cluster.shared::cta.b64 P, [%0], %1, 0x989680;\n\t"
        "@P bra.uni DONE_%=;\n\t"
        "bra.uni WAIT_%=;\n\t"
        "DONE_%=: \n\t"
        "}"
        :: "r"(addr), "r"(parity) : "memory");
}

// packed f32x2 ops (per-lane rn semantics == scalar rn; bit-exact)
#define ADD2(out, a, b) asm("add.rn.f32x2 %0, %1, %2;" : "=l"(out) : "l"(a), "l"(b))
#define MUL2(out, a, b) asm("mul.rn.f32x2 %0, %1, %2;" : "=l"(out) : "l"(a), "l"(b))
#define FMA2(out, a, b, c) asm("fma.rn.f32x2 %0, %1, %2, %3;" : "=l"(out) : "l"(a), "l"(b), "l"(c))
#define PACK2(out, lo, hi) asm("mov.b64 %0, {%1, %2};" : "=l"(out) : "f"(lo), "f"(hi))
#define UNPACK2(lo, hi, in) asm("mov.b64 {%0, %1}, %2;" : "=f"(lo), "=f"(hi) : "l"(in))

// Reference-exact squared distance (verified bit-exact; DO NOT TOUCH):
//   d = fma(dz,dz, fma(dx,dx, rn(dy*dy)))   and  dx computed as rn(px + (-cx))

// -------------- fused FPS + streaming-gather kernel ---------------
// Grid: BATCH*CSZ blocks, cluster (CSZ,1,1) = one batch per cluster.
// FPS loop as R15. Output gather is STREAMED inside the loop: rows are
// striped across ranks (e = rank + 8k); ~17 threads per CTA each issue one
// LDG for the current winner and retire last iteration's value with one STG.
// The LDG latency hides under the next iteration; no serial gather tail.
__global__ void __launch_bounds__(TPB, 1) __cluster_dims__(CSZ, 1, 1)
fps_gather_kernel(const float* __restrict__ xyz,
                  const float* __restrict__ feat,
                  float* __restrict__ out)
{
    const int rank  = (int)cluster_rank_();
    const int batch = blockIdx.x / CSZ;
    const float* __restrict__ xb = xyz + (size_t)batch * 3 * NPTS;
    const int tid  = threadIdx.x;
    const int base = rank * PPC;

    // all-to-all messages, double-buffered by iteration parity
    __shared__ __align__(16) unsigned long long s_msgkey[2][CSZ];  // (dist<<32)|enc
    __shared__ __align__(16) float4 s_msgxyz[2][CSZ];              // x,y,z,pad
    // stage-1 partials: combined (dist<<32)|enc per warp
    __shared__ unsigned long long s_key[NWARP];
    __shared__ unsigned long long s_mbar;
    // coord mirror (read-only after init; winner coord lookup)
    __shared__ float s_px[PPC], s_py[PPC], s_pz[PPC];

    // register-resident packed point data + scalar min-dists
    unsigned long long px2[NPAIR], py2[NPAIR], pz2[NPAIR];
    float dd[PPT];
#pragma unroll
    for (int jp = 0; jp < NPAIR; jp++) {
        int l0 = (2 * jp) * TPB + tid;
        int l1 = l0 + TPB;
        float x0 = __ldg(xb + base + l0), x1 = __ldg(xb + base + l1);
        float y0 = __ldg(xb + NPTS + base + l0), y1 = __ldg(xb + NPTS + base + l1);
        float z0 = __ldg(xb + 2 * NPTS + base + l0), z1 = __ldg(xb + 2 * NPTS + base + l1);
        PACK2(px2[jp], x0, x1);
        PACK2(py2[jp], y0, y1);
        PACK2(pz2[jp], z0, z1);
        s_px[l0] = x0; s_px[l1] = x1;
        s_py[l0] = y0; s_py[l1] = y1;
        s_pz[l0] = z0; s_pz[l1] = z1;
        dd[2 * jp] = 1e10f;
        dd[2 * jp + 1] = 1e10f;
    }

    if (tid == 0) mbar_init(smem_u32(&s_mbar), CSZ);

    // initial centroid = point 0
    float cx = __ldg(xb);
    float cy = __ldg(xb + NPTS);
    float cz = __ldg(xb + 2 * NPTS);

    // ---- streaming-gather setup (rows striped across ranks) ----
    // thread (tid-32) handles row e = rank + 8*(tid-32), e < MROWS
    const int gk = tid - 32;
    const int ge = rank + CSZ * gk;
    const bool gact = (gk >= 0) && (ge < MROWS);
    const float* gin = nullptr;
    float* gout = nullptr;
    if (gact) {
        const long P1 = (long)BATCH * 3 * MPTS;
        if (ge < 3) {
            gin  = xb + (size_t)ge * NPTS;
            gout = out + ((long)batch * 3 + ge) * MPTS;
        } else {
            gin  = feat + (size_t)batch * CINCH * NPTS + (size_t)(ge - 3) * NPTS;
            gout = out + P1 + ((long)batch * CINCH + (ge - 3)) * MPTS;
        }
    }
    float gval = 0.0f;

    __syncthreads();
    cluster_sync_();  // once: mbarriers + mirrors initialized cluster-wide

    const unsigned mbarAddr = smem_u32(&s_mbar);

    // hoisted remote addresses (loop-invariant per lane; used by lanes 0..7)
    const int dl = tid & 31;   // destination lane -> rank
    const unsigned rka0 = mapa_rank(smem_u32(&s_msgkey[0][rank]), dl);
    const unsigned rka1 = mapa_rank(smem_u32(&s_msgkey[1][rank]), dl);
    const unsigned rca0 = mapa_rank(smem_u32(&s_msgxyz[0][rank]), dl);
    const unsigned rca1 = mapa_rank(smem_u32(&s_msgxyz[1][rank]), dl);
    const unsigned rma  = mapa_rank(mbarAddr, dl);

    for (int it = 1; it < MPTS; ++it) {
        // packed negated centroid (rn(a + (-b)) == rn(a - b), bit-exact)
        unsigned long long ncx2, ncy2, ncz2;
        {
            float nx = -cx, ny = -cy, nz = -cz;
            PACK2(ncx2, nx, nx);
            PACK2(ncy2, ny, ny);
            PACK2(ncz2, nz, nz);
        }

        // ---- phase 1: distance + dd update, NO argmax bookkeeping ----
#pragma unroll
        for (int jp = 0; jp < NPAIR; jp++) {
            unsigned long long dx2, dy2, dz2, t2;
            ADD2(dx2, px2[jp], ncx2);
            ADD2(dy2, py2[jp], ncy2);
            ADD2(dz2, pz2[jp], ncz2);
            MUL2(t2, dy2, dy2);               // rn(dy*dy)
            FMA2(t2, dx2, dx2, t2);           // fma(dx,dx, .)
            FMA2(t2, dz2, dz2, t2);           // fma(dz,dz, .)
            float d0, d1;
            UNPACK2(d0, d1, t2);
            dd[2 * jp]     = fminf(dd[2 * jp], d0);
            dd[2 * jp + 1] = fminf(dd[2 * jp + 1], d1);
        }

        // ---- phase 2: thread max via fmaxf tree (depth 3) ----
        float m01 = fmaxf(dd[0], dd[1]);
        float m23 = fmaxf(dd[2], dd[3]);
        float m45 = fmaxf(dd[4], dd[5]);
        float m67 = fmaxf(dd[6], dd[7]);
        float m03 = fmaxf(m01, m23);
        float m47 = fmaxf(m45, m67);
        unsigned bestd = __float_as_uint(fmaxf(m03, m47));  // bits monotone (>=0)

        // ---- stage 1: warp max, then lazy lowest-index recovery ----
        unsigned wmax = redux_max_u32(bestd);
        unsigned cand = 0xFFFFFFFFu;
#pragma unroll
        for (int j = PPT - 1; j >= 0; j--) {   // descending j: final sel = lowest j
            if (__float_as_uint(dd[j]) == wmax)
                cand = (unsigned)(base + j * TPB + tid);
        }
        unsigned wwin = redux_min_u32(cand);
        if ((tid & 31) == 0) {
            s_key[tid >> 5] = ((unsigned long long)wmax << 32) | (32767u - wwin);
        }
        __syncthreads();   // all partials visible

        const int buf = it & 1;

        // ---- stage 2 (warp0): 1 LDS.64 + 2x redux; lanes 0..7 push ----
        if (tid < 32) {
            unsigned long long p = (tid < NWARP) ? s_key[tid] : 0ull;
            unsigned d = (unsigned)(p >> 32);
            unsigned e = (unsigned)p;
            unsigned m  = redux_max_u32(d);
            unsigned ce = (d == m) ? e : 0u;
            unsigned em = redux_max_u32(ce);
            if (tid < CSZ) {
                unsigned long long key = ((unsigned long long)m << 32) | em;
                int li = (32767 - (int)em) - base;   // CTA-local winner offset
                float wx = s_px[li], wy = s_py[li], wz = s_pz[li];
                unsigned long long xy, zp;
                PACK2(xy, wx, wy);
                zp = (unsigned long long)__float_as_uint(wz);
                unsigned ka = buf ? rka1 : rka0;
                unsigned ca = buf ? rca1 : rca0;
                st_cluster_u64(ka, key);
                st_cluster_u64(ca, xy);
                st_cluster_u64(ca + 8, zp);
                mbar_arrive_remote(rma);
            }
        }

        // ---- all warps wait for the 8 CTA candidates (phase parity) ----
        mbar_wait(mbarAddr, (unsigned)((it - 1) & 1));

        // ---- extract global winner: tree compare (depth 3) ----
        const ulonglong2* kp = (const ulonglong2*)&s_msgkey[buf][0];
        ulonglong2 k01 = kp[0], k23 = kp[1], k45 = kp[2], k67 = kp[3];
        unsigned long long a0 = k01.x; int i0 = 0;
        if (k01.y > a0) { a0 = k01.y; i0 = 1; }
        unsigned long long a1 = k23.x; int i1 = 2;
        if (k23.y > a1) { a1 = k23.y; i1 = 3; }
        unsigned long long a2 = k45.x; int i2 = 4;
        if (k45.y > a2) { a2 = k45.y; i2 = 5; }
        unsigned long long a3 = k67.x; int i3 = 6;
        if (k67.y > a3) { a3 = k67.y; i3 = 7; }
        if (a1 > a0) { a0 = a1; i0 = i1; }
        if (a3 > a2) { a2 = a3; i2 = i3; }
        if (a2 > a0) { a0 = a2; i0 = i2; }
        float4 co = s_msgxyz[buf][i0];
        cx = co.x; cy = co.y; cz = co.z;

        // ---- streaming gather: retire winner[it-1], load winner[it] ----
        if (gact) {
            int widx = 32767 - (int)(a0 & 0xFFFFull);
            if (it > 1) gout[it - 1] = gval;    // value loaded last iteration
            gval = __ldg(gin + widx);            // latency hides under next iter
        }
    }

    // ---- streaming-gather tail: last winner + seed point (m = 0, idx = 0) ----
    if (gact) {
        gout[MPTS - 1] = gval;
        gout[0] = __ldg(gin);
    }
}

extern "C" void kernel_launch(void* const* d_in, const int* in_sizes, int n_in,
                              void* d_out, int out_size)
{
    // Defensive: pick xyz by element count (B*3*N = 786432)
    const float* xyz;
    const float* feat;
    if (in_sizes[0] == BATCH * 3 * NPTS) {
        xyz  = (const float*)d_in[0];
        feat = (const float*)d_in[1];
    } else {
        xyz  = (const float*)d_in[1];
        feat = (const float*)d_in[0];
    }
    float* out = (float*)d_out;

    fps_gather_kernel<<<BATCH * CSZ, TPB>>>(xyz, feat, out);
}

// round 17
// speedup vs baseline: 1.6621x; 1.6621x over previous
#include <cuda_runtime.h>
#include <cstdint>

// Problem constants
#define BATCH 8
#define NPTS  32768
#define MPTS  (NPTS / 4)     // 8192
#define CINCH 128
#define MROWS (3 + CINCH)    // 131 output rows per batch

// FPS kernel config: one cluster of CSZ CTAs per batch
#define CSZ   8
#define TPB   512
#define PPC   (NPTS / CSZ)           // points per CTA = 4096
#define PPT   (PPC / TPB)            // points per thread = 8
#define NPAIR (PPT / 2)              // f32x2 pairs per thread = 4
#define NWARP (TPB / 32)             // 16
#define MPC   (MPTS / CSZ)           // sampled points gathered per CTA = 1024

// ---------------- helpers ----------------
__device__ __forceinline__ unsigned smem_u32(const void* p) {
    return (unsigned)__cvta_generic_to_shared(p);
}
__device__ __forceinline__ void cluster_sync_() {
    asm volatile("barrier.cluster.arrive.aligned;" ::: "memory");
    asm volatile("barrier.cluster.wait.aligned;" ::: "memory");
}
__device__ __forceinline__ unsigned mapa_rank(unsigned local_addr, int r) {
    unsigned ret;
    asm("mapa.shared::cluster.u32 %0, %1, %2;" : "=r"(ret) : "r"(local_addr), "r"(r));
    return ret;
}
__device__ __forceinline__ void st_cluster_u64(unsigned addr, unsigned long long v) {
    asm volatile("st.shared::cluster.b64 [%0], %1;" :: "r"(addr), "l"(v) : "memory");
}
__device__ __forceinline__ unsigned cluster_rank_() {
    unsigned r;
    asm("mov.u32 %0, %%cluster_ctarank;" : "=r"(r));
    return r;
}
__device__ __forceinline__ unsigned redux_max_u32(unsigned v) {
    unsigned r;
    asm volatile("redux.sync.max.u32 %0, %1, 0xffffffff;" : "=r"(r) : "r"(v));
    return r;
}
__device__ __forceinline__ unsigned redux_min_u32(unsigned v) {
    unsigned r;
    asm volatile("redux.sync.min.u32 %0, %1, 0xffffffff;" : "=r"(r) : "r"(v));
    return r;
}

// mbarrier ops
__device__ __forceinline__ void mbar_init(unsigned addr, unsigned count) {
    asm volatile("mbarrier.init.shared.b64 [%0], %1;" :: "r"(addr), "r"(count) : "memory");
}
__device__ __forceinline__ void mbar_arrive_remote(unsigned remote_addr) {
    asm volatile("mbarrier.arrive.release.cluster.shared::cluster.b64 _, [%0];"
                 :: "r"(remote_addr) : "memory");
}
__device__ __forceinline__ void mbar_wait(unsigned addr, unsigned parity) {
    asm volatile(
        "{\n\t"
        ".reg .pred P;\n\t"
        "WAIT_%=: \n\t"
        "mbarrier.try_wait.parity.acquire.cluster.shared::cta.b64 P, [%0], %1, 0x989680;\n\t"
        "@P bra.uni DONE_%=;\n\t"
        "bra.uni WAIT_%=;\n\t"
        "DONE_%=: \n\t"
        "}"
        :: "r"(addr), "r"(parity) : "memory");
}

// packed f32x2 ops (per-lane rn semantics == scalar rn; bit-exact)
#define ADD2(out, a, b) asm("add.rn.f32x2 %0, %1, %2;" : "=l"(out) : "l"(a), "l"(b))
#define MUL2(out, a, b) asm("mul.rn.f32x2 %0, %1, %2;" : "=l"(out) : "l"(a), "l"(b))
#define FMA2(out, a, b, c) asm("fma.rn.f32x2 %0, %1, %2, %3;" : "=l"(out) : "l"(a), "l"(b), "l"(c))
#define PACK2(out, lo, hi) asm("mov.b64 %0, {%1, %2};" : "=l"(out) : "f"(lo), "f"(hi))
#define UNPACK2(lo, hi, in) asm("mov.b64 {%0, %1}, %2;" : "=f"(lo), "=f"(hi) : "l"(in))

// Reference-exact squared distance (verified bit-exact; DO NOT TOUCH):
//   d = fma(dz,dz, fma(dx,dx, rn(dy*dy)))   and  dx computed as rn(px + (-cx))

// -------------- fused FPS + gather kernel ---------------
// Grid: BATCH*CSZ blocks, cluster (CSZ,1,1) = one batch per cluster.
// R15 structure (best known: 7443us). Sender transmits PRE-NEGATED coords in
// the same two u64 stores, removing 3 FNEG from the receiver's critical path.
// Gather runs as the post-loop tail (in-loop global traffic poisons the
// cluster-fabric path; measured R16).
__global__ void __launch_bounds__(TPB, 1) __cluster_dims__(CSZ, 1, 1)
fps_gather_kernel(const float* __restrict__ xyz,
                  const float* __restrict__ feat,
                  float* __restrict__ out)
{
    const int rank  = (int)cluster_rank_();
    const int batch = blockIdx.x / CSZ;
    const float* __restrict__ xb = xyz + (size_t)batch * 3 * NPTS;
    const int tid  = threadIdx.x;
    const int base = rank * PPC;

    // all-to-all messages, double-buffered by iteration parity
    __shared__ __align__(16) unsigned long long s_msgkey[2][CSZ];  // (dist<<32)|enc
    __shared__ __align__(16) ulonglong2 s_msgc[2][CSZ];            // {-x,-y} packed, {-z}
    // stage-1 partials: combined (dist<<32)|enc per warp
    __shared__ unsigned long long s_key[NWARP];
    __shared__ unsigned long long s_mbar;
    // coord mirror (read-only after init; winner coord lookup)
    __shared__ float s_px[PPC], s_py[PPC], s_pz[PPC];
    // full selected-index list (every CTA keeps its own copy)
    __shared__ int s_idx[MPTS];

    // register-resident packed point data + scalar min-dists
    unsigned long long px2[NPAIR], py2[NPAIR], pz2[NPAIR];
    float dd[PPT];
#pragma unroll
    for (int jp = 0; jp < NPAIR; jp++) {
        int l0 = (2 * jp) * TPB + tid;
        int l1 = l0 + TPB;
        float x0 = __ldg(xb + base + l0), x1 = __ldg(xb + base + l1);
        float y0 = __ldg(xb + NPTS + base + l0), y1 = __ldg(xb + NPTS + base + l1);
        float z0 = __ldg(xb + 2 * NPTS + base + l0), z1 = __ldg(xb + 2 * NPTS + base + l1);
        PACK2(px2[jp], x0, x1);
        PACK2(py2[jp], y0, y1);
        PACK2(pz2[jp], z0, z1);
        s_px[l0] = x0; s_px[l1] = x1;
        s_py[l0] = y0; s_py[l1] = y1;
        s_pz[l0] = z0; s_pz[l1] = z1;
        dd[2 * jp] = 1e10f;
        dd[2 * jp + 1] = 1e10f;
    }

    if (tid == 0) {
        mbar_init(smem_u32(&s_mbar), CSZ);
        s_idx[0] = 0;   // seed point 0
    }

    // initial negated centroid = -point 0
    float ncx = -__ldg(xb);
    float ncy = -__ldg(xb + NPTS);
    float ncz = -__ldg(xb + 2 * NPTS);

    __syncthreads();
    cluster_sync_();  // once: mbarriers + mirrors initialized cluster-wide

    const unsigned mbarAddr = smem_u32(&s_mbar);

    // hoisted remote addresses (loop-invariant per lane; used by lanes 0..7)
    const int dl = tid & 31;   // destination lane -> rank
    const unsigned rka0 = mapa_rank(smem_u32(&s_msgkey[0][rank]), dl);
    const unsigned rka1 = mapa_rank(smem_u32(&s_msgkey[1][rank]), dl);
    const unsigned rca0 = mapa_rank(smem_u32(&s_msgc[0][rank]), dl);
    const unsigned rca1 = mapa_rank(smem_u32(&s_msgc[1][rank]), dl);
    const unsigned rma  = mapa_rank(mbarAddr, dl);

    for (int it = 1; it < MPTS; ++it) {
        // packed negated centroid (rn(a + (-b)) == rn(a - b), bit-exact)
        unsigned long long ncx2, ncy2, ncz2;
        PACK2(ncx2, ncx, ncx);
        PACK2(ncy2, ncy, ncy);
        PACK2(ncz2, ncz, ncz);

        // ---- phase 1: distance + dd update, NO argmax bookkeeping ----
#pragma unroll
        for (int jp = 0; jp < NPAIR; jp++) {
            unsigned long long dx2, dy2, dz2, t2;
            ADD2(dx2, px2[jp], ncx2);
            ADD2(dy2, py2[jp], ncy2);
            ADD2(dz2, pz2[jp], ncz2);
            MUL2(t2, dy2, dy2);               // rn(dy*dy)
            FMA2(t2, dx2, dx2, t2);           // fma(dx,dx, .)
            FMA2(t2, dz2, dz2, t2);           // fma(dz,dz, .)
            float d0, d1;
            UNPACK2(d0, d1, t2);
            dd[2 * jp]     = fminf(dd[2 * jp], d0);
            dd[2 * jp + 1] = fminf(dd[2 * jp + 1], d1);
        }

        // ---- phase 2: thread max via fmaxf tree (depth 3) ----
        float m01 = fmaxf(dd[0], dd[1]);
        float m23 = fmaxf(dd[2], dd[3]);
        float m45 = fmaxf(dd[4], dd[5]);
        float m67 = fmaxf(dd[6], dd[7]);
        float m03 = fmaxf(m01, m23);
        float m47 = fmaxf(m45, m67);
        unsigned bestd = __float_as_uint(fmaxf(m03, m47));  // bits monotone (>=0)

        // ---- stage 1: warp max, then lazy lowest-index recovery ----
        unsigned wmax = redux_max_u32(bestd);
        unsigned cand = 0xFFFFFFFFu;
#pragma unroll
        for (int j = PPT - 1; j >= 0; j--) {   // descending j: final sel = lowest j
            if (__float_as_uint(dd[j]) == wmax)
                cand = (unsigned)(base + j * TPB + tid);
        }
        unsigned wwin = redux_min_u32(cand);
        if ((tid & 31) == 0) {
            s_key[tid >> 5] = ((unsigned long long)wmax << 32) | (32767u - wwin);
        }
        __syncthreads();   // all partials visible

        const int buf = it & 1;

        // ---- stage 2 (warp0): 1 LDS.64 + 2x redux; lanes 0..7 push ----
        if (tid < 32) {
            unsigned long long p = (tid < NWARP) ? s_key[tid] : 0ull;
            unsigned d = (unsigned)(p >> 32);
            unsigned e = (unsigned)p;
            unsigned m  = redux_max_u32(d);
            unsigned ce = (d == m) ? e : 0u;
            unsigned em = redux_max_u32(ce);
            if (tid < CSZ) {
                unsigned long long key = ((unsigned long long)m << 32) | em;
                int li = (32767 - (int)em) - base;   // CTA-local winner offset
                // pre-negated coords: receiver uses them directly
                float nx = -s_px[li], ny = -s_py[li], nz = -s_pz[li];
                unsigned long long nxy, nzp;
                PACK2(nxy, nx, ny);
                nzp = (unsigned long long)__float_as_uint(nz);
                unsigned ka = buf ? rka1 : rka0;
                unsigned ca = buf ? rca1 : rca0;
                st_cluster_u64(ka, key);
                st_cluster_u64(ca, nxy);
                st_cluster_u64(ca + 8, nzp);
                mbar_arrive_remote(rma);
            }
        }

        // ---- all warps wait for the 8 CTA candidates (phase parity) ----
        mbar_wait(mbarAddr, (unsigned)((it - 1) & 1));

        // ---- extract global winner: tree compare (depth 3) ----
        const ulonglong2* kp = (const ulonglong2*)&s_msgkey[buf][0];
        ulonglong2 k01 = kp[0], k23 = kp[1], k45 = kp[2], k67 = kp[3];
        unsigned long long a0 = k01.x; int i0 = 0;
        if (k01.y > a0) { a0 = k01.y; i0 = 1; }
        unsigned long long a1 = k23.x; int i1 = 2;
        if (k23.y > a1) { a1 = k23.y; i1 = 3; }
        unsigned long long a2 = k45.x; int i2 = 4;
        if (k45.y > a2) { a2 = k45.y; i2 = 5; }
        unsigned long long a3 = k67.x; int i3 = 6;
        if (k67.y > a3) { a3 = k67.y; i3 = 7; }
        if (a1 > a0) { a0 = a1; i0 = i1; }
        if (a3 > a2) { a2 = a3; i2 = i3; }
        if (a2 > a0) { a0 = a2; i0 = i2; }
        ulonglong2 co = s_msgc[buf][i0];      // one LDS.128: {-x,-y}, {-z}
        UNPACK2(ncx, ncy, co.x);
        ncz = __uint_as_float((unsigned)co.y);

        if (tid == 0) s_idx[it] = 32767 - (int)(a0 & 0xFFFFull);
    }

    // ================= fused gather (post-loop tail) =================
    __syncthreads();   // s_idx complete in this CTA

    const float* __restrict__ fb = feat + (size_t)batch * CINCH * NPTS;
    const long P1 = (long)BATCH * 3 * MPTS;
    const int m0 = rank * MPC;   // this CTA's slice of sampled points

    for (int e = tid; e < MROWS * MPC; e += TPB) {
        int c  = e >> 10;           // MPC = 1024
        int ml = e & (MPC - 1);
        int m  = m0 + ml;
        int idx = s_idx[m];
        float v;
        long o;
        if (c < 3) {
            v = __ldg(xb + (size_t)c * NPTS + idx);
            o = ((long)batch * 3 + c) * MPTS + m;
        } else {
            v = __ldg(fb + (size_t)(c - 3) * NPTS + idx);
            o = P1 + ((long)batch * CINCH + (c - 3)) * MPTS + m;
        }
        out[o] = v;
    }
}

extern "C" void kernel_launch(void* const* d_in, const int* in_sizes, int n_in,
                              void* d_out, int out_size)
{
    // Defensive: pick xyz by element count (B*3*N = 786432)
    const float* xyz;
    const float* feat;
    if (in_sizes[0] == BATCH * 3 * NPTS) {
        xyz  = (const float*)d_in[0];
        feat = (const float*)d_in[1];
    } else {
        xyz  = (const float*)d_in[1];
        feat = (const float*)d_in[0];
    }
    float* out = (float*)d_out;

    fps_gather_kernel<<<BATCH * CSZ, TPB>>>(xyz, feat, out);
}